// round 12
// baseline (speedup 1.0000x reference)
#include <cuda_runtime.h>
#include <cuda_fp16.h>
#include <math.h>
#include <stdint.h>

#define BB   2
#define SS   2048
#define EE   1024
#define HH   16
#define DD   64
#define MTOT (BB*SS)   // 4096
#define MEG  1048576

// fp16 scratch (allocation-free rule: __device__ globals)
__device__ __half g_Qh[(size_t)MTOT*EE];
__device__ __half g_Kh[(size_t)MTOT*EE];
__device__ __half g_Vh[(size_t)MTOT*EE];
__device__ __half g_WQ[(size_t)EE*EE];
__device__ __half g_WK[(size_t)EE*EE];
__device__ __half g_WV[(size_t)EE*EE];
__device__ __half g_WO[(size_t)EE*EE];
__device__ __half g_qh[(size_t)BB*HH*SS*DD];   // head-major, pre-scaled by SMSC
__device__ __half g_kh[(size_t)BB*HH*SS*DD];
__device__ __half g_vh[(size_t)BB*HH*SS*DD];
__device__ __half g_attn[(size_t)MTOT*EE];
__device__ uint32_t g_mbits[(size_t)BB*SS*SS/32];

#define SMSC 0.18033688f   // 0.125 * log2(e), folded into Q projection

// ---------------------------------------------------------------------------
__device__ __forceinline__ uint32_t smaddr(const void* p) {
    return (uint32_t)__cvta_generic_to_shared(p);
}
__device__ __forceinline__ void ldsm4(uint32_t* r, uint32_t a) {
    asm volatile("ldmatrix.sync.aligned.m8n8.x4.shared.b16 {%0,%1,%2,%3}, [%4];"
                 : "=r"(r[0]), "=r"(r[1]), "=r"(r[2]), "=r"(r[3]) : "r"(a));
}
__device__ __forceinline__ void ldsm4t(uint32_t* r, uint32_t a) {
    asm volatile("ldmatrix.sync.aligned.m8n8.x4.trans.shared.b16 {%0,%1,%2,%3}, [%4];"
                 : "=r"(r[0]), "=r"(r[1]), "=r"(r[2]), "=r"(r[3]) : "r"(a));
}
__device__ __forceinline__ void mmaf16(float c[4], const uint32_t a[4],
                                       uint32_t b0, uint32_t b1) {
    asm volatile(
        "mma.sync.aligned.m16n8k16.row.col.f32.f16.f16.f32 "
        "{%0,%1,%2,%3}, {%4,%5,%6,%7}, {%8,%9}, {%0,%1,%2,%3};"
        : "+f"(c[0]), "+f"(c[1]), "+f"(c[2]), "+f"(c[3])
        : "r"(a[0]), "r"(a[1]), "r"(a[2]), "r"(a[3]), "r"(b0), "r"(b1));
}
__device__ __forceinline__ void cpa16(void* sm, const void* gm) {
    uint32_t s = (uint32_t)__cvta_generic_to_shared(sm);
    asm volatile("cp.async.ca.shared.global [%0], [%1], 16;" :: "r"(s), "l"(gm));
}
__device__ __forceinline__ void cp_commit() { asm volatile("cp.async.commit_group;"); }
template<int N> __device__ __forceinline__ void cp_wait() {
    asm volatile("cp.async.wait_group %0;" :: "n"(N));
}
__device__ __forceinline__ float ex2(float x) {
    float r;
    asm("ex2.approx.f32 %0, %1;" : "=f"(r) : "f"(x));
    return r;
}
// 2-bit mask -> half2 zero-mask (bit0 zeroes low half, bit1 zeroes high half)
__device__ __forceinline__ uint32_t zm2(uint32_t bits2) {
    uint32_t m = 0xFFFFFFFFu;
    if (bits2 & 1u) m &= 0xFFFF0000u;
    if (bits2 & 2u) m &= 0x0000FFFFu;
    return m;
}
__device__ __forceinline__ uint32_t packh2(float a, float b) {
    __half2 h = __floats2half2_rn(a, b);
    return *(uint32_t*)&h;
}
#define ONES2 0x3C003C00u   // half2(1.0, 1.0)

// ---------------------------------------------------------------------------
__global__ void pack_mask_kernel(const int* __restrict__ mask,
                                 uint32_t* __restrict__ bits) {
    int idx = blockIdx.x * 256 + threadIdx.x;
    unsigned b = __ballot_sync(0xffffffffu, mask[idx] != 0);
    if ((threadIdx.x & 31) == 0) bits[idx >> 5] = b;
}

// fp32 -> fp16 conversion of all GEMM inputs. 16 slots of 1M elements.
__global__ void __launch_bounds__(256)
cvt_kernel(const float* __restrict__ Q, const float* __restrict__ K,
           const float* __restrict__ V, const float* __restrict__ WQ,
           const float* __restrict__ WK, const float* __restrict__ WV,
           const float* __restrict__ WO)
{
    int slot = blockIdx.y;
    const float* src;
    __half* dst;
    if      (slot < 4)  { src = Q  + (size_t)slot * MEG;       dst = g_Qh + (size_t)slot * MEG; }
    else if (slot < 8)  { src = K  + (size_t)(slot - 4) * MEG; dst = g_Kh + (size_t)(slot - 4) * MEG; }
    else if (slot < 12) { src = V  + (size_t)(slot - 8) * MEG; dst = g_Vh + (size_t)(slot - 8) * MEG; }
    else if (slot == 12){ src = WQ; dst = g_WQ; }
    else if (slot == 13){ src = WK; dst = g_WK; }
    else if (slot == 14){ src = WV; dst = g_WV; }
    else                { src = WO; dst = g_WO; }
    size_t i = ((size_t)blockIdx.x * 256 + threadIdx.x) * 4;
    float4 v = *(const float4*)&src[i];
    __half2 h0 = __floats2half2_rn(v.x, v.y);
    __half2 h1 = __floats2half2_rn(v.z, v.w);
    *(uint2*)&dst[i] = make_uint2(*(uint32_t*)&h0, *(uint32_t*)&h1);
}

// ---------------------------------------------------------------------------
// fp16 GEMM body: C[M,N] = A[M,K] * W[N,K]^T  (M=4096, N=K=1024)
// Block 128x128, 8 warps (4m x 2n), warp 32x64. BK=32, 3-stage cp.async.
// ---------------------------------------------------------------------------
#define PSTH   40
#define STAGES 3

__device__ __forceinline__ void
proj_body(const __half* __restrict__ A, const __half* __restrict__ W,
          void* __restrict__ Cout, int mode, float oscale)
{
    extern __shared__ __half hsm[];
    __half* AS = hsm;                         // [3][128][40]
    __half* WS = hsm + STAGES * 128 * PSTH;   // [3][128][40]

    const int tid  = threadIdx.x;
    const int lane = tid & 31;
    const int wid  = tid >> 5;
    const int wm   = wid & 3;
    const int wn   = wid >> 2;
    const int gid  = lane >> 2;
    const int tig  = lane & 3;
    const int m0   = blockIdx.y * 128;
    const int n0   = blockIdx.x * 128;

    auto load_stage = [&](int st, int k0) {
        __half* as = AS + st * 128 * PSTH;
        __half* ws = WS + st * 128 * PSTH;
        #pragma unroll
        for (int p = 0; p < 2; p++) {
            int idx = tid + p * 256;
            int r = idx >> 2, c = (idx & 3) * 8;
            cpa16(&as[r * PSTH + c], &A[(size_t)(m0 + r) * EE + k0 + c]);
            cpa16(&ws[r * PSTH + c], &W[(size_t)(n0 + r) * EE + k0 + c]);
        }
    };

    float acc[2][8][4] = {};

    load_stage(0, 0);  cp_commit();
    load_stage(1, 32); cp_commit();

    const int KT = EE / 32;  // 32
    for (int kt = 0; kt < KT; kt++) {
        cp_wait<1>();
        __syncthreads();
        int st = kt % STAGES;
        if (kt + 2 < KT) load_stage((kt + 2) % STAGES, (kt + 2) * 32);
        cp_commit();

        const __half* as = AS + st * 128 * PSTH;
        const __half* ws = WS + st * 128 * PSTH;
        #pragma unroll
        for (int kk = 0; kk < 2; kk++) {
            int kb = kk * 16;
            uint32_t a[2][4];
            #pragma unroll
            for (int i = 0; i < 2; i++) {
                int row = wm * 32 + i * 16 + (lane & 15);
                ldsm4(a[i], smaddr(&as[row * PSTH + kb + ((lane >> 4) * 8)]));
            }
            uint32_t bf[4][4];
            #pragma unroll
            for (int jp = 0; jp < 4; jp++) {
                int nrow = wn * 64 + jp * 16 + ((lane >> 4) & 1) * 8 + (lane & 7);
                int kcol = kb + ((lane >> 3) & 1) * 8;
                ldsm4(bf[jp], smaddr(&ws[nrow * PSTH + kcol]));
            }
            #pragma unroll
            for (int jp = 0; jp < 4; jp++)
                #pragma unroll
                for (int i = 0; i < 2; i++) {
                    mmaf16(acc[i][2 * jp],     a[i], bf[jp][0], bf[jp][1]);
                    mmaf16(acc[i][2 * jp + 1], a[i], bf[jp][2], bf[jp][3]);
                }
        }
    }

    #pragma unroll
    for (int i = 0; i < 2; i++) {
        #pragma unroll
        for (int j = 0; j < 8; j++) {
            int m = m0 + wm * 32 + i * 16 + gid;
            int n = n0 + wn * 64 + j * 8 + tig * 2;
            float v0 = acc[i][j][0] * oscale, v1 = acc[i][j][1] * oscale;
            float v2 = acc[i][j][2] * oscale, v3 = acc[i][j][3] * oscale;
            if (mode == 0) {
                float* C = (float*)Cout;
                *(float2*)&C[(size_t)m * EE + n] = make_float2(v0, v1);
                *(float2*)&C[(size_t)(m + 8) * EE + n] = make_float2(v2, v3);
            } else {
                __half* C = (__half*)Cout;
                int h = n >> 6, d = n & 63;
                int b1_ = m >> 11, s1 = m & (SS - 1);
                *(__half2*)&C[(((size_t)(b1_ * HH + h)) * SS + s1) * DD + d] =
                    __floats2half2_rn(v0, v1);
                int b2 = (m + 8) >> 11, s2 = (m + 8) & (SS - 1);
                *(__half2*)&C[(((size_t)(b2 * HH + h)) * SS + s2) * DD + d] =
                    __floats2half2_rn(v2, v3);
            }
        }
    }
}

__global__ void __launch_bounds__(256, 2)
qkv_proj_kernel(__half* __restrict__ qh, __half* __restrict__ kh,
                __half* __restrict__ vh)
{
    int z = blockIdx.z;
    const __half* A = (z == 0) ? g_Qh : (z == 1) ? g_Kh : g_Vh;
    const __half* W = (z == 0) ? g_WQ : (z == 1) ? g_WK : g_WV;
    __half* C       = (z == 0) ? qh   : (z == 1) ? kh   : vh;
    proj_body(A, W, C, 1, (z == 0) ? SMSC : 1.0f);
}

__global__ void __launch_bounds__(256, 2)
out_proj_kernel(float* __restrict__ C)
{
    proj_body(g_attn, g_WO, C, 0, 1.0f);
}

// ---------------------------------------------------------------------------
// Flash attention, fp16 MMA, bias-free softmax, P in registers, l via
// ones-MMA. Block = (b,h) x 128 q-rows, 4 warps x 32 rows, 2 CTAs/SM.
// This round: hoisted LDSM offsets (koff/voff regs), 3-stage K/V cp.async
// pipeline, and exp/pack/l/PV chunked per k-slice so P fragments are
// transient.
// ---------------------------------------------------------------------------
#define FSTH   72
#define KVSTG  3
#define KVBYT  (64 * FSTH * 2)   // bytes per K (or V) stage buffer

__global__ void __launch_bounds__(128, 2)
flash_tc_kernel(const uint32_t* __restrict__ mbits)
{
    extern __shared__ __half fsm[];
    __half* qs  = fsm;                    // [128][72]: Q staging (prologue only)
    __half* ksb = fsm + 128 * FSTH;       // [3][64][72]
    __half* vsb = ksb + KVSTG * 64 * FSTH;// [3][64][72]

    const int tid  = threadIdx.x;
    const int lane = tid & 31;
    const int w    = tid >> 5;            // 0..3
    const int gid  = lane >> 2;
    const int tig  = lane & 3;
    const int bh   = blockIdx.y;
    const int b    = bh >> 4, h = bh & 15;
    const int q0   = blockIdx.x * 128;

    const __half* qp = g_qh + (size_t)bh * SS * DD;
    const __half* kp = g_kh + (size_t)bh * SS * DD;
    const __half* vp = g_vh + (size_t)bh * SS * DD;

    const uint32_t* mrow[2][2];
    #pragma unroll
    for (int u = 0; u < 2; u++)
        #pragma unroll
        for (int v = 0; v < 2; v++)
            mrow[u][v] = mbits +
                ((size_t)(b * SS + q0 + w * 32 + u * 16 + gid + v * 8) << 6);

    auto load_kv = [&](int st, int kv0) {
        __half* ks = ksb + st * 64 * FSTH;
        __half* vs = vsb + st * 64 * FSTH;
        #pragma unroll
        for (int p = 0; p < 4; p++) {
            int idx = tid + p * 128;
            int r = idx >> 3, c = (idx & 7) * 8;
            cpa16(&ks[r * FSTH + c], &kp[(size_t)(kv0 + r) * DD + c]);
            cpa16(&vs[r * FSTH + c], &vp[(size_t)(kv0 + r) * DD + c]);
        }
    };

    // stage Q
    #pragma unroll
    for (int p = 0; p < 8; p++) {
        int idx = tid + p * 128;
        int r = idx >> 3, c = (idx & 7) * 8;
        cpa16(&qs[r * FSTH + c], &qp[(size_t)(q0 + r) * DD + c]);
    }
    load_kv(0, 0);
    cp_commit();
    load_kv(1, 64);
    cp_commit();
    cp_wait<1>();
    __syncthreads();

    // persistent Q fragments (own 32 rows)
    uint32_t qa[2][4][4];
    #pragma unroll
    for (int u = 0; u < 2; u++) {
        int row = w * 32 + u * 16 + (lane & 15);
        #pragma unroll
        for (int t = 0; t < 4; t++)
            ldsm4(qa[u][t], smaddr(&qs[row * FSTH + t * 16 + (lane >> 4) * 8]));
    }

    // hoisted per-thread LDSM byte offsets
    const uint32_t ksu = smaddr(ksb);
    const uint32_t vsu = smaddr(vsb);
    uint32_t koff[4], voff[4];
    #pragma unroll
    for (int jp = 0; jp < 4; jp++) {
        int nrow = jp * 16 + ((lane >> 4) & 1) * 8 + (lane & 7);
        koff[jp] = (uint32_t)((nrow * FSTH + ((lane >> 3) & 1) * 8) * 2);
        int kvrow = ((lane >> 3) & 1) * 8 + (lane & 7);
        int dcol  = jp * 16 + ((lane >> 4) & 1) * 8;
        voff[jp] = (uint32_t)((kvrow * FSTH + dcol) * 2);
    }

    float o[2][8][4] = {};
    float lacc[2][4] = {};

    const int NT = SS / 64;  // 32
    for (int t = 0; t < NT; t++) {
        cp_wait<1>();
        __syncthreads();
        if (t + 2 < NT) load_kv((t + 2) % KVSTG, (t + 2) * 64);
        cp_commit();

        const int st = t % KVSTG;
        const uint32_t kbase = ksu + st * KVBYT;
        const uint32_t vbase = vsu + st * KVBYT;

        // S = Q @ K^T  (pre-scaled scores)
        float s[2][8][4] = {};
        #pragma unroll
        for (int tt = 0; tt < 4; tt++) {
            #pragma unroll
            for (int jp = 0; jp < 4; jp++) {
                uint32_t kf[4];
                ldsm4(kf, kbase + koff[jp] + tt * 32);
                #pragma unroll
                for (int u = 0; u < 2; u++) {
                    mmaf16(s[u][2 * jp],     qa[u][tt], kf[0], kf[1]);
                    mmaf16(s[u][2 * jp + 1], qa[u][tt], kf[2], kf[3]);
                }
            }
        }

        // mask words for this tile
        const int wq = t * 2;
        uint32_t mw[2][2][2];
        #pragma unroll
        for (int u = 0; u < 2; u++) {
            mw[u][0][0] = mrow[u][0][wq];  mw[u][0][1] = mrow[u][0][wq + 1];
            mw[u][1][0] = mrow[u][1][wq];  mw[u][1][1] = mrow[u][1][wq + 1];
        }

        // per k-slice: exp -> pack+mask -> l-MMA -> PV (P transient)
        #pragma unroll
        for (int tt = 0; tt < 4; tt++) {
            const int j0 = 2 * tt, j1 = 2 * tt + 1;
            const int c00 = (j0 * 8 + tig * 2) & 31;
            const int c01 = (j1 * 8 + tig * 2) & 31;
            uint32_t pa[2][4];
            #pragma unroll
            for (int u = 0; u < 2; u++) {
                uint32_t wrA0 = mw[u][0][j0 >> 2], wrB0 = mw[u][1][j0 >> 2];
                uint32_t wrA1 = mw[u][0][j1 >> 2], wrB1 = mw[u][1][j1 >> 2];
                pa[u][0] = packh2(ex2(s[u][j0][0]), ex2(s[u][j0][1])) & zm2((wrA0 >> c00) & 3u);
                pa[u][1] = packh2(ex2(s[u][j0][2]), ex2(s[u][j0][3])) & zm2((wrB0 >> c00) & 3u);
                pa[u][2] = packh2(ex2(s[u][j1][0]), ex2(s[u][j1][1])) & zm2((wrA1 >> c01) & 3u);
                pa[u][3] = packh2(ex2(s[u][j1][2]), ex2(s[u][j1][3])) & zm2((wrB1 >> c01) & 3u);
                mmaf16(lacc[u], pa[u], ONES2, ONES2);
            }
            #pragma unroll
            for (int jp = 0; jp < 4; jp++) {
                uint32_t vf[4];
                ldsm4t(vf, vbase + voff[jp] + tt * (16 * FSTH * 2));
                #pragma unroll
                for (int u = 0; u < 2; u++) {
                    mmaf16(o[u][2 * jp],     pa[u], vf[0], vf[1]);
                    mmaf16(o[u][2 * jp + 1], pa[u], vf[2], vf[3]);
                }
            }
        }
    }

    // normalize + scatter to [B,S,E] (fp16)
    #pragma unroll
    for (int u = 0; u < 2; u++) {
        float i0 = 1.0f / lacc[u][0], i1 = 1.0f / lacc[u][2];
        int row = q0 + w * 32 + u * 16 + gid;
        #pragma unroll
        for (int j = 0; j < 8; j++) {
            int c0 = h * 64 + j * 8 + tig * 2;
            *(__half2*)&g_attn[((size_t)(b * SS + row)) * EE + c0] =
                __floats2half2_rn(o[u][j][0] * i0, o[u][j][1] * i0);
            *(__half2*)&g_attn[((size_t)(b * SS + row + 8)) * EE + c0] =
                __floats2half2_rn(o[u][j][2] * i1, o[u][j][3] * i1);
        }
    }
}

// ---------------------------------------------------------------------------
extern "C" void kernel_launch(void* const* d_in, const int* in_sizes, int n_in,
                              void* d_out, int out_size)
{
    (void)in_sizes; (void)n_in; (void)out_size;
    const float* Q    = (const float*)d_in[0];
    const float* K    = (const float*)d_in[1];
    const float* V    = (const float*)d_in[2];
    const int*   mask = (const int*)  d_in[3];
    const float* WQ   = (const float*)d_in[4];
    const float* WK   = (const float*)d_in[5];
    const float* WV   = (const float*)d_in[6];
    const float* WO   = (const float*)d_in[7];
    float* out = (float*)d_out;

    __half *qh, *kh, *vh;
    uint32_t* mbits;
    cudaGetSymbolAddress((void**)&qh,    g_qh);
    cudaGetSymbolAddress((void**)&kh,    g_kh);
    cudaGetSymbolAddress((void**)&vh,    g_vh);
    cudaGetSymbolAddress((void**)&mbits, g_mbits);

    const int PROJ_SMEM  = STAGES * (128 + 128) * PSTH * (int)sizeof(__half);      // 61440
    const int FLASH_SMEM = (128 + 2 * KVSTG * 64) * FSTH * (int)sizeof(__half);    // 73728
    cudaFuncSetAttribute(qkv_proj_kernel,
                         cudaFuncAttributeMaxDynamicSharedMemorySize, PROJ_SMEM);
    cudaFuncSetAttribute(out_proj_kernel,
                         cudaFuncAttributeMaxDynamicSharedMemorySize, PROJ_SMEM);
    cudaFuncSetAttribute(flash_tc_kernel,
                         cudaFuncAttributeMaxDynamicSharedMemorySize, FLASH_SMEM);

    pack_mask_kernel<<<BB * SS * SS / 256, 256>>>(mask, mbits);
    cvt_kernel<<<dim3(1024, 16), 256>>>(Q, K, V, WQ, WK, WV, WO);

    qkv_proj_kernel<<<dim3(EE / 128, MTOT / 128, 3), 256, PROJ_SMEM>>>(qh, kh, vh);

    flash_tc_kernel<<<dim3(SS / 128, BB * HH), 128, FLASH_SMEM>>>(mbits);

    out_proj_kernel<<<dim3(EE / 128, MTOT / 128), 256, PROJ_SMEM>>>(out);
}

// round 13
// speedup vs baseline: 1.0338x; 1.0338x over previous
#include <cuda_runtime.h>
#include <cuda_fp16.h>
#include <math.h>
#include <stdint.h>

#define BB   2
#define SS   2048
#define EE   1024
#define HH   16
#define DD   64
#define MTOT (BB*SS)   // 4096
#define MEG  1048576

// fp16 scratch (allocation-free rule: __device__ globals)
__device__ __half g_Qh[(size_t)MTOT*EE];
__device__ __half g_Kh[(size_t)MTOT*EE];
__device__ __half g_Vh[(size_t)MTOT*EE];
__device__ __half g_WQ[(size_t)EE*EE];
__device__ __half g_WK[(size_t)EE*EE];
__device__ __half g_WV[(size_t)EE*EE];
__device__ __half g_WO[(size_t)EE*EE];
__device__ __half g_qh[(size_t)BB*HH*SS*DD];   // head-major, pre-scaled by SMSC
__device__ __half g_kh[(size_t)BB*HH*SS*DD];
__device__ __half g_vh[(size_t)BB*HH*SS*DD];
__device__ __half g_attn[(size_t)MTOT*EE];
__device__ uint32_t g_mbits[(size_t)BB*SS*SS/32];

#define SMSC 0.18033688f   // 0.125 * log2(e), folded into Q projection

// ---------------------------------------------------------------------------
__device__ __forceinline__ uint32_t smaddr(const void* p) {
    return (uint32_t)__cvta_generic_to_shared(p);
}
__device__ __forceinline__ void ldsm4(uint32_t* r, uint32_t a) {
    asm volatile("ldmatrix.sync.aligned.m8n8.x4.shared.b16 {%0,%1,%2,%3}, [%4];"
                 : "=r"(r[0]), "=r"(r[1]), "=r"(r[2]), "=r"(r[3]) : "r"(a));
}
__device__ __forceinline__ void ldsm4t(uint32_t* r, uint32_t a) {
    asm volatile("ldmatrix.sync.aligned.m8n8.x4.trans.shared.b16 {%0,%1,%2,%3}, [%4];"
                 : "=r"(r[0]), "=r"(r[1]), "=r"(r[2]), "=r"(r[3]) : "r"(a));
}
__device__ __forceinline__ void mmaf16(float c[4], const uint32_t a[4],
                                       uint32_t b0, uint32_t b1) {
    asm volatile(
        "mma.sync.aligned.m16n8k16.row.col.f32.f16.f16.f32 "
        "{%0,%1,%2,%3}, {%4,%5,%6,%7}, {%8,%9}, {%0,%1,%2,%3};"
        : "+f"(c[0]), "+f"(c[1]), "+f"(c[2]), "+f"(c[3])
        : "r"(a[0]), "r"(a[1]), "r"(a[2]), "r"(a[3]), "r"(b0), "r"(b1));
}
__device__ __forceinline__ void cpa16(void* sm, const void* gm) {
    uint32_t s = (uint32_t)__cvta_generic_to_shared(sm);
    asm volatile("cp.async.ca.shared.global [%0], [%1], 16;" :: "r"(s), "l"(gm));
}
__device__ __forceinline__ void cp_commit() { asm volatile("cp.async.commit_group;"); }
template<int N> __device__ __forceinline__ void cp_wait() {
    asm volatile("cp.async.wait_group %0;" :: "n"(N));
}
__device__ __forceinline__ float ex2(float x) {
    float r;
    asm("ex2.approx.f32 %0, %1;" : "=f"(r) : "f"(x));
    return r;
}
// 2-bit mask -> half2 zero-mask (bit0 zeroes low half, bit1 zeroes high half)
__device__ __forceinline__ uint32_t zm2(uint32_t bits2) {
    uint32_t m = 0xFFFFFFFFu;
    if (bits2 & 1u) m &= 0xFFFF0000u;
    if (bits2 & 2u) m &= 0x0000FFFFu;
    return m;
}
__device__ __forceinline__ uint32_t packh2(float a, float b) {
    __half2 h = __floats2half2_rn(a, b);
    return *(uint32_t*)&h;
}
#define ONES2 0x3C003C00u   // half2(1.0, 1.0)

// ---------------------------------------------------------------------------
__global__ void pack_mask_kernel(const int* __restrict__ mask,
                                 uint32_t* __restrict__ bits) {
    int idx = blockIdx.x * 256 + threadIdx.x;
    unsigned b = __ballot_sync(0xffffffffu, mask[idx] != 0);
    if ((threadIdx.x & 31) == 0) bits[idx >> 5] = b;
}

// fp32 -> fp16 conversion of all GEMM inputs. 16 slots of 1M elements.
__global__ void __launch_bounds__(256)
cvt_kernel(const float* __restrict__ Q, const float* __restrict__ K,
           const float* __restrict__ V, const float* __restrict__ WQ,
           const float* __restrict__ WK, const float* __restrict__ WV,
           const float* __restrict__ WO)
{
    int slot = blockIdx.y;
    const float* src;
    __half* dst;
    if      (slot < 4)  { src = Q  + (size_t)slot * MEG;       dst = g_Qh + (size_t)slot * MEG; }
    else if (slot < 8)  { src = K  + (size_t)(slot - 4) * MEG; dst = g_Kh + (size_t)(slot - 4) * MEG; }
    else if (slot < 12) { src = V  + (size_t)(slot - 8) * MEG; dst = g_Vh + (size_t)(slot - 8) * MEG; }
    else if (slot == 12){ src = WQ; dst = g_WQ; }
    else if (slot == 13){ src = WK; dst = g_WK; }
    else if (slot == 14){ src = WV; dst = g_WV; }
    else                { src = WO; dst = g_WO; }
    size_t i = ((size_t)blockIdx.x * 256 + threadIdx.x) * 4;
    float4 v = *(const float4*)&src[i];
    __half2 h0 = __floats2half2_rn(v.x, v.y);
    __half2 h1 = __floats2half2_rn(v.z, v.w);
    *(uint2*)&dst[i] = make_uint2(*(uint32_t*)&h0, *(uint32_t*)&h1);
}

// ---------------------------------------------------------------------------
// fp16 GEMM body: C[M,N] = A[M,K] * W[N,K]^T  (M=4096, N=K=1024)
// Block 128x128, 8 warps (4m x 2n), warp 32x64. BK=32, 3-stage cp.async.
// ---------------------------------------------------------------------------
#define PSTH   40
#define STAGES 3

__device__ __forceinline__ void
proj_body(const __half* __restrict__ A, const __half* __restrict__ W,
          void* __restrict__ Cout, int mode, float oscale)
{
    extern __shared__ __half hsm[];
    __half* AS = hsm;                         // [3][128][40]
    __half* WS = hsm + STAGES * 128 * PSTH;   // [3][128][40]

    const int tid  = threadIdx.x;
    const int lane = tid & 31;
    const int wid  = tid >> 5;
    const int wm   = wid & 3;
    const int wn   = wid >> 2;
    const int gid  = lane >> 2;
    const int tig  = lane & 3;
    const int m0   = blockIdx.y * 128;
    const int n0   = blockIdx.x * 128;

    auto load_stage = [&](int st, int k0) {
        __half* as = AS + st * 128 * PSTH;
        __half* ws = WS + st * 128 * PSTH;
        #pragma unroll
        for (int p = 0; p < 2; p++) {
            int idx = tid + p * 256;
            int r = idx >> 2, c = (idx & 3) * 8;
            cpa16(&as[r * PSTH + c], &A[(size_t)(m0 + r) * EE + k0 + c]);
            cpa16(&ws[r * PSTH + c], &W[(size_t)(n0 + r) * EE + k0 + c]);
        }
    };

    float acc[2][8][4] = {};

    load_stage(0, 0);  cp_commit();
    load_stage(1, 32); cp_commit();

    const int KT = EE / 32;  // 32
    for (int kt = 0; kt < KT; kt++) {
        cp_wait<1>();
        __syncthreads();
        int st = kt % STAGES;
        if (kt + 2 < KT) load_stage((kt + 2) % STAGES, (kt + 2) * 32);
        cp_commit();

        const __half* as = AS + st * 128 * PSTH;
        const __half* ws = WS + st * 128 * PSTH;
        #pragma unroll
        for (int kk = 0; kk < 2; kk++) {
            int kb = kk * 16;
            uint32_t a[2][4];
            #pragma unroll
            for (int i = 0; i < 2; i++) {
                int row = wm * 32 + i * 16 + (lane & 15);
                ldsm4(a[i], smaddr(&as[row * PSTH + kb + ((lane >> 4) * 8)]));
            }
            uint32_t bf[4][4];
            #pragma unroll
            for (int jp = 0; jp < 4; jp++) {
                int nrow = wn * 64 + jp * 16 + ((lane >> 4) & 1) * 8 + (lane & 7);
                int kcol = kb + ((lane >> 3) & 1) * 8;
                ldsm4(bf[jp], smaddr(&ws[nrow * PSTH + kcol]));
            }
            #pragma unroll
            for (int jp = 0; jp < 4; jp++)
                #pragma unroll
                for (int i = 0; i < 2; i++) {
                    mmaf16(acc[i][2 * jp],     a[i], bf[jp][0], bf[jp][1]);
                    mmaf16(acc[i][2 * jp + 1], a[i], bf[jp][2], bf[jp][3]);
                }
        }
    }

    #pragma unroll
    for (int i = 0; i < 2; i++) {
        #pragma unroll
        for (int j = 0; j < 8; j++) {
            int m = m0 + wm * 32 + i * 16 + gid;
            int n = n0 + wn * 64 + j * 8 + tig * 2;
            float v0 = acc[i][j][0] * oscale, v1 = acc[i][j][1] * oscale;
            float v2 = acc[i][j][2] * oscale, v3 = acc[i][j][3] * oscale;
            if (mode == 0) {
                float* C = (float*)Cout;
                *(float2*)&C[(size_t)m * EE + n] = make_float2(v0, v1);
                *(float2*)&C[(size_t)(m + 8) * EE + n] = make_float2(v2, v3);
            } else {
                __half* C = (__half*)Cout;
                int h = n >> 6, d = n & 63;
                int b1_ = m >> 11, s1 = m & (SS - 1);
                *(__half2*)&C[(((size_t)(b1_ * HH + h)) * SS + s1) * DD + d] =
                    __floats2half2_rn(v0, v1);
                int b2 = (m + 8) >> 11, s2 = (m + 8) & (SS - 1);
                *(__half2*)&C[(((size_t)(b2 * HH + h)) * SS + s2) * DD + d] =
                    __floats2half2_rn(v2, v3);
            }
        }
    }
}

__global__ void __launch_bounds__(256, 2)
qkv_proj_kernel(__half* __restrict__ qh, __half* __restrict__ kh,
                __half* __restrict__ vh)
{
    int z = blockIdx.z;
    const __half* A = (z == 0) ? g_Qh : (z == 1) ? g_Kh : g_Vh;
    const __half* W = (z == 0) ? g_WQ : (z == 1) ? g_WK : g_WV;
    __half* C       = (z == 0) ? qh   : (z == 1) ? kh   : vh;
    proj_body(A, W, C, 1, (z == 0) ? SMSC : 1.0f);
}

__global__ void __launch_bounds__(256, 2)
out_proj_kernel(float* __restrict__ C)
{
    proj_body(g_attn, g_WO, C, 0, 1.0f);
}

// ---------------------------------------------------------------------------
// Flash attention, fp16 MMA, bias-free softmax, P in registers, l via
// ones-MMA. Block = (b,h) x 128 q-rows, 4 warps x 32 rows.
// This round: kv tile processed in TWO 32-col halves so the live S set is
// 32 regs (not 64) -> __launch_bounds__(128,3) = 3 CTAs/SM (12 warps)
// with r11's lean LDSM traffic. Identical instruction totals & math to r11.
// ---------------------------------------------------------------------------
#define FSTH 72

__global__ void __launch_bounds__(128, 3)
flash_tc_kernel(const uint32_t* __restrict__ mbits)
{
    extern __shared__ __half fsm[];
    __half* qs  = fsm;                    // [128][72]: Q staging (prologue only)
    __half* ksb = fsm + 128 * FSTH;       // [2][64][72]
    __half* vsb = ksb + 2 * 64 * FSTH;    // [2][64][72]

    const int tid  = threadIdx.x;
    const int lane = tid & 31;
    const int w    = tid >> 5;            // 0..3
    const int gid  = lane >> 2;
    const int tig  = lane & 3;
    const int bh   = blockIdx.y;
    const int b    = bh >> 4, h = bh & 15;
    const int q0   = blockIdx.x * 128;

    const __half* qp = g_qh + (size_t)bh * SS * DD;
    const __half* kp = g_kh + (size_t)bh * SS * DD;
    const __half* vp = g_vh + (size_t)bh * SS * DD;

    const uint32_t* mrow[2][2];
    #pragma unroll
    for (int u = 0; u < 2; u++)
        #pragma unroll
        for (int v = 0; v < 2; v++)
            mrow[u][v] = mbits +
                ((size_t)(b * SS + q0 + w * 32 + u * 16 + gid + v * 8) << 6);

    auto load_kv = [&](int st, int kv0) {
        __half* ks = ksb + st * 64 * FSTH;
        __half* vs = vsb + st * 64 * FSTH;
        #pragma unroll
        for (int p = 0; p < 4; p++) {
            int idx = tid + p * 128;
            int r = idx >> 3, c = (idx & 7) * 8;
            cpa16(&ks[r * FSTH + c], &kp[(size_t)(kv0 + r) * DD + c]);
            cpa16(&vs[r * FSTH + c], &vp[(size_t)(kv0 + r) * DD + c]);
        }
    };

    // stage Q
    #pragma unroll
    for (int p = 0; p < 8; p++) {
        int idx = tid + p * 128;
        int r = idx >> 3, c = (idx & 7) * 8;
        cpa16(&qs[r * FSTH + c], &qp[(size_t)(q0 + r) * DD + c]);
    }
    load_kv(0, 0);
    cp_commit();
    cp_wait<0>();
    __syncthreads();

    // persistent Q fragments (own 32 rows)
    uint32_t qa[2][4][4];
    #pragma unroll
    for (int u = 0; u < 2; u++) {
        int row = w * 32 + u * 16 + (lane & 15);
        #pragma unroll
        for (int t = 0; t < 4; t++)
            ldsm4(qa[u][t], smaddr(&qs[row * FSTH + t * 16 + (lane >> 4) * 8]));
    }

    float o[2][8][4] = {};
    float lacc[2][4] = {};

    const int NT = SS / 64;  // 32
    for (int t = 0; t < NT; t++) {
        cp_wait<0>();
        __syncthreads();
        if (t + 1 < NT) load_kv((t + 1) & 1, (t + 1) * 64);
        cp_commit();

        const __half* ks = ksb + (t & 1) * 64 * FSTH;
        const __half* vs = vsb + (t & 1) * 64 * FSTH;

        // process kv tile in two 32-col halves (S live set = 32 regs)
        #pragma unroll
        for (int hh = 0; hh < 2; hh++) {
            // S = Q @ K^T for kv cols [hh*32, hh*32+32)
            float s[2][4][4] = {};
            #pragma unroll
            for (int tt = 0; tt < 4; tt++) {
                #pragma unroll
                for (int jl = 0; jl < 2; jl++) {
                    int jp = 2 * hh + jl;
                    uint32_t kf[4];
                    int nrow = jp * 16 + ((lane >> 4) & 1) * 8 + (lane & 7);
                    int kcol = tt * 16 + ((lane >> 3) & 1) * 8;
                    ldsm4(kf, smaddr(&ks[nrow * FSTH + kcol]));
                    #pragma unroll
                    for (int u = 0; u < 2; u++) {
                        mmaf16(s[u][2 * jl],     qa[u][tt], kf[0], kf[1]);
                        mmaf16(s[u][2 * jl + 1], qa[u][tt], kf[2], kf[3]);
                    }
                }
            }

            // one mask word per row for this 32-col half
            const int wq = t * 2 + hh;
            #pragma unroll
            for (int ttl = 0; ttl < 2; ttl++) {
                const int j0 = 2 * ttl, j1 = 2 * ttl + 1;
                const int c00 = j0 * 8 + tig * 2;
                const int c01 = j1 * 8 + tig * 2;
                const int gtt = hh * 2 + ttl;   // global 16-row kv slice
                uint32_t pa[2][4];
                #pragma unroll
                for (int u = 0; u < 2; u++) {
                    uint32_t wa = mrow[u][0][wq];
                    uint32_t wb = mrow[u][1][wq];
                    pa[u][0] = packh2(ex2(s[u][j0][0]), ex2(s[u][j0][1])) & zm2((wa >> c00) & 3u);
                    pa[u][1] = packh2(ex2(s[u][j0][2]), ex2(s[u][j0][3])) & zm2((wb >> c00) & 3u);
                    pa[u][2] = packh2(ex2(s[u][j1][0]), ex2(s[u][j1][1])) & zm2((wa >> c01) & 3u);
                    pa[u][3] = packh2(ex2(s[u][j1][2]), ex2(s[u][j1][3])) & zm2((wb >> c01) & 3u);
                    mmaf16(lacc[u], pa[u], ONES2, ONES2);
                }
                // O += P @ V for this kv slice (all d columns)
                #pragma unroll
                for (int jp = 0; jp < 4; jp++) {
                    uint32_t vf[4];
                    int kvrow = gtt * 16 + ((lane >> 3) & 1) * 8 + (lane & 7);
                    int dcol  = jp * 16 + ((lane >> 4) & 1) * 8;
                    ldsm4t(vf, smaddr(&vs[kvrow * FSTH + dcol]));
                    #pragma unroll
                    for (int u = 0; u < 2; u++) {
                        mmaf16(o[u][2 * jp],     pa[u], vf[0], vf[1]);
                        mmaf16(o[u][2 * jp + 1], pa[u], vf[2], vf[3]);
                    }
                }
            }
        }
    }

    // normalize + scatter to [B,S,E] (fp16)
    #pragma unroll
    for (int u = 0; u < 2; u++) {
        float i0 = 1.0f / lacc[u][0], i1 = 1.0f / lacc[u][2];
        int row = q0 + w * 32 + u * 16 + gid;
        #pragma unroll
        for (int j = 0; j < 8; j++) {
            int c0 = h * 64 + j * 8 + tig * 2;
            *(__half2*)&g_attn[((size_t)(b * SS + row)) * EE + c0] =
                __floats2half2_rn(o[u][j][0] * i0, o[u][j][1] * i0);
            *(__half2*)&g_attn[((size_t)(b * SS + row + 8)) * EE + c0] =
                __floats2half2_rn(o[u][j][2] * i1, o[u][j][3] * i1);
        }
    }
}

// ---------------------------------------------------------------------------
extern "C" void kernel_launch(void* const* d_in, const int* in_sizes, int n_in,
                              void* d_out, int out_size)
{
    (void)in_sizes; (void)n_in; (void)out_size;
    const float* Q    = (const float*)d_in[0];
    const float* K    = (const float*)d_in[1];
    const float* V    = (const float*)d_in[2];
    const int*   mask = (const int*)  d_in[3];
    const float* WQ   = (const float*)d_in[4];
    const float* WK   = (const float*)d_in[5];
    const float* WV   = (const float*)d_in[6];
    const float* WO   = (const float*)d_in[7];
    float* out = (float*)d_out;

    __half *qh, *kh, *vh;
    uint32_t* mbits;
    cudaGetSymbolAddress((void**)&qh,    g_qh);
    cudaGetSymbolAddress((void**)&kh,    g_kh);
    cudaGetSymbolAddress((void**)&vh,    g_vh);
    cudaGetSymbolAddress((void**)&mbits, g_mbits);

    const int PROJ_SMEM  = STAGES * (128 + 128) * PSTH * (int)sizeof(__half);   // 61440
    const int FLASH_SMEM = (128 + 4 * 64) * FSTH * (int)sizeof(__half);         // 55296
    cudaFuncSetAttribute(qkv_proj_kernel,
                         cudaFuncAttributeMaxDynamicSharedMemorySize, PROJ_SMEM);
    cudaFuncSetAttribute(out_proj_kernel,
                         cudaFuncAttributeMaxDynamicSharedMemorySize, PROJ_SMEM);
    cudaFuncSetAttribute(flash_tc_kernel,
                         cudaFuncAttributeMaxDynamicSharedMemorySize, FLASH_SMEM);

    pack_mask_kernel<<<BB * SS * SS / 256, 256>>>(mask, mbits);
    cvt_kernel<<<dim3(1024, 16), 256>>>(Q, K, V, WQ, WK, WV, WO);

    qkv_proj_kernel<<<dim3(EE / 128, MTOT / 128, 3), 256, PROJ_SMEM>>>(qh, kh, vh);

    flash_tc_kernel<<<dim3(SS / 128, BB * HH), 128, FLASH_SMEM>>>(mbits);

    out_proj_kernel<<<dim3(EE / 128, MTOT / 128), 256, PROJ_SMEM>>>(out);
}

// round 15
// speedup vs baseline: 1.0779x; 1.0426x over previous
#include <cuda_runtime.h>
#include <cuda_fp16.h>
#include <math.h>
#include <stdint.h>

#define BB   2
#define SS   2048
#define EE   1024
#define HH   16
#define DD   64
#define MTOT (BB*SS)   // 4096
#define MEG  1048576

// fp16 scratch (allocation-free rule: __device__ globals)
__device__ __half g_Qh[(size_t)MTOT*EE];
__device__ __half g_Kh[(size_t)MTOT*EE];
__device__ __half g_Vh[(size_t)MTOT*EE];
__device__ __half g_WQ[(size_t)EE*EE];
__device__ __half g_WK[(size_t)EE*EE];
__device__ __half g_WV[(size_t)EE*EE];
__device__ __half g_WO[(size_t)EE*EE];
__device__ __half g_qh[(size_t)BB*HH*SS*DD];   // head-major, pre-scaled by SMSC
__device__ __half g_kh[(size_t)BB*HH*SS*DD];
__device__ __half g_vh[(size_t)BB*HH*SS*DD];
__device__ __half g_attn[(size_t)MTOT*EE];
__device__ uint32_t g_mbits[(size_t)BB*SS*SS/32];
// split-KV partials (fp32, unnormalized)
__device__ float g_po[2][(size_t)BB*HH*SS*DD];
__device__ float g_pl[2][(size_t)BB*HH*SS];

#define SMSC 0.18033688f   // 0.125 * log2(e), folded into Q projection

// ---------------------------------------------------------------------------
__device__ __forceinline__ uint32_t smaddr(const void* p) {
    return (uint32_t)__cvta_generic_to_shared(p);
}
__device__ __forceinline__ void ldsm4(uint32_t* r, uint32_t a) {
    asm volatile("ldmatrix.sync.aligned.m8n8.x4.shared.b16 {%0,%1,%2,%3}, [%4];"
                 : "=r"(r[0]), "=r"(r[1]), "=r"(r[2]), "=r"(r[3]) : "r"(a));
}
__device__ __forceinline__ void ldsm4t(uint32_t* r, uint32_t a) {
    asm volatile("ldmatrix.sync.aligned.m8n8.x4.trans.shared.b16 {%0,%1,%2,%3}, [%4];"
                 : "=r"(r[0]), "=r"(r[1]), "=r"(r[2]), "=r"(r[3]) : "r"(a));
}
__device__ __forceinline__ void mmaf16(float c[4], const uint32_t a[4],
                                       uint32_t b0, uint32_t b1) {
    asm volatile(
        "mma.sync.aligned.m16n8k16.row.col.f32.f16.f16.f32 "
        "{%0,%1,%2,%3}, {%4,%5,%6,%7}, {%8,%9}, {%0,%1,%2,%3};"
        : "+f"(c[0]), "+f"(c[1]), "+f"(c[2]), "+f"(c[3])
        : "r"(a[0]), "r"(a[1]), "r"(a[2]), "r"(a[3]), "r"(b0), "r"(b1));
}
__device__ __forceinline__ void cpa16(void* sm, const void* gm) {
    uint32_t s = (uint32_t)__cvta_generic_to_shared(sm);
    asm volatile("cp.async.ca.shared.global [%0], [%1], 16;" :: "r"(s), "l"(gm));
}
__device__ __forceinline__ void cp_commit() { asm volatile("cp.async.commit_group;"); }
template<int N> __device__ __forceinline__ void cp_wait() {
    asm volatile("cp.async.wait_group %0;" :: "n"(N));
}
__device__ __forceinline__ float ex2(float x) {
    float r;
    asm("ex2.approx.f32 %0, %1;" : "=f"(r) : "f"(x));
    return r;
}
__device__ __forceinline__ uint32_t zm2(uint32_t bits2) {
    uint32_t m = 0xFFFFFFFFu;
    if (bits2 & 1u) m &= 0xFFFF0000u;
    if (bits2 & 2u) m &= 0x0000FFFFu;
    return m;
}
__device__ __forceinline__ uint32_t packh2(float a, float b) {
    __half2 h = __floats2half2_rn(a, b);
    return *(uint32_t*)&h;
}
#define ONES2 0x3C003C00u   // half2(1.0, 1.0)

// ---------------------------------------------------------------------------
__global__ void pack_mask_kernel(const int* __restrict__ mask,
                                 uint32_t* __restrict__ bits) {
    int idx = blockIdx.x * 256 + threadIdx.x;
    unsigned b = __ballot_sync(0xffffffffu, mask[idx] != 0);
    if ((threadIdx.x & 31) == 0) bits[idx >> 5] = b;
}

// fp32 -> fp16 conversion of all GEMM inputs. 16 slots of 1M elements.
__global__ void __launch_bounds__(256)
cvt_kernel(const float* __restrict__ Q, const float* __restrict__ K,
           const float* __restrict__ V, const float* __restrict__ WQ,
           const float* __restrict__ WK, const float* __restrict__ WV,
           const float* __restrict__ WO)
{
    int slot = blockIdx.y;
    const float* src;
    __half* dst;
    if      (slot < 4)  { src = Q  + (size_t)slot * MEG;       dst = g_Qh + (size_t)slot * MEG; }
    else if (slot < 8)  { src = K  + (size_t)(slot - 4) * MEG; dst = g_Kh + (size_t)(slot - 4) * MEG; }
    else if (slot < 12) { src = V  + (size_t)(slot - 8) * MEG; dst = g_Vh + (size_t)(slot - 8) * MEG; }
    else if (slot == 12){ src = WQ; dst = g_WQ; }
    else if (slot == 13){ src = WK; dst = g_WK; }
    else if (slot == 14){ src = WV; dst = g_WV; }
    else                { src = WO; dst = g_WO; }
    size_t i = ((size_t)blockIdx.x * 256 + threadIdx.x) * 4;
    float4 v = *(const float4*)&src[i];
    __half2 h0 = __floats2half2_rn(v.x, v.y);
    __half2 h1 = __floats2half2_rn(v.z, v.w);
    *(uint2*)&dst[i] = make_uint2(*(uint32_t*)&h0, *(uint32_t*)&h1);
}

// ---------------------------------------------------------------------------
// fp16 GEMM body: C[M,N] = A[M,K] * W[N,K]^T  (M=4096, N=K=1024)
// Block 128x128, 8 warps (4m x 2n), warp 32x64. BK=32, 3-stage cp.async.
// ---------------------------------------------------------------------------
#define PSTH   40
#define STAGES 3

__device__ __forceinline__ void
proj_body(const __half* __restrict__ A, const __half* __restrict__ W,
          void* __restrict__ Cout, int mode, float oscale)
{
    extern __shared__ __half hsm[];
    __half* AS = hsm;                         // [3][128][40]
    __half* WS = hsm + STAGES * 128 * PSTH;   // [3][128][40]

    const int tid  = threadIdx.x;
    const int lane = tid & 31;
    const int wid  = tid >> 5;
    const int wm   = wid & 3;
    const int wn   = wid >> 2;
    const int gid  = lane >> 2;
    const int tig  = lane & 3;
    const int m0   = blockIdx.y * 128;
    const int n0   = blockIdx.x * 128;

    auto load_stage = [&](int st, int k0) {
        __half* as = AS + st * 128 * PSTH;
        __half* ws = WS + st * 128 * PSTH;
        #pragma unroll
        for (int p = 0; p < 2; p++) {
            int idx = tid + p * 256;
            int r = idx >> 2, c = (idx & 3) * 8;
            cpa16(&as[r * PSTH + c], &A[(size_t)(m0 + r) * EE + k0 + c]);
            cpa16(&ws[r * PSTH + c], &W[(size_t)(n0 + r) * EE + k0 + c]);
        }
    };

    float acc[2][8][4] = {};

    load_stage(0, 0);  cp_commit();
    load_stage(1, 32); cp_commit();

    const int KT = EE / 32;  // 32
    for (int kt = 0; kt < KT; kt++) {
        cp_wait<1>();
        __syncthreads();
        int st = kt % STAGES;
        if (kt + 2 < KT) load_stage((kt + 2) % STAGES, (kt + 2) * 32);
        cp_commit();

        const __half* as = AS + st * 128 * PSTH;
        const __half* ws = WS + st * 128 * PSTH;
        #pragma unroll
        for (int kk = 0; kk < 2; kk++) {
            int kb = kk * 16;
            uint32_t a[2][4];
            #pragma unroll
            for (int i = 0; i < 2; i++) {
                int row = wm * 32 + i * 16 + (lane & 15);
                ldsm4(a[i], smaddr(&as[row * PSTH + kb + ((lane >> 4) * 8)]));
            }
            uint32_t bf[4][4];
            #pragma unroll
            for (int jp = 0; jp < 4; jp++) {
                int nrow = wn * 64 + jp * 16 + ((lane >> 4) & 1) * 8 + (lane & 7);
                int kcol = kb + ((lane >> 3) & 1) * 8;
                ldsm4(bf[jp], smaddr(&ws[nrow * PSTH + kcol]));
            }
            #pragma unroll
            for (int jp = 0; jp < 4; jp++)
                #pragma unroll
                for (int i = 0; i < 2; i++) {
                    mmaf16(acc[i][2 * jp],     a[i], bf[jp][0], bf[jp][1]);
                    mmaf16(acc[i][2 * jp + 1], a[i], bf[jp][2], bf[jp][3]);
                }
        }
    }

    #pragma unroll
    for (int i = 0; i < 2; i++) {
        #pragma unroll
        for (int j = 0; j < 8; j++) {
            int m = m0 + wm * 32 + i * 16 + gid;
            int n = n0 + wn * 64 + j * 8 + tig * 2;
            float v0 = acc[i][j][0] * oscale, v1 = acc[i][j][1] * oscale;
            float v2 = acc[i][j][2] * oscale, v3 = acc[i][j][3] * oscale;
            if (mode == 0) {
                float* C = (float*)Cout;
                *(float2*)&C[(size_t)m * EE + n] = make_float2(v0, v1);
                *(float2*)&C[(size_t)(m + 8) * EE + n] = make_float2(v2, v3);
            } else {
                __half* C = (__half*)Cout;
                int h = n >> 6, d = n & 63;
                int b1_ = m >> 11, s1 = m & (SS - 1);
                *(__half2*)&C[(((size_t)(b1_ * HH + h)) * SS + s1) * DD + d] =
                    __floats2half2_rn(v0, v1);
                int b2 = (m + 8) >> 11, s2 = (m + 8) & (SS - 1);
                *(__half2*)&C[(((size_t)(b2 * HH + h)) * SS + s2) * DD + d] =
                    __floats2half2_rn(v2, v3);
            }
        }
    }
}

__global__ void __launch_bounds__(256, 2)
qkv_proj_kernel(__half* __restrict__ qh, __half* __restrict__ kh,
                __half* __restrict__ vh)
{
    int z = blockIdx.z;
    const __half* A = (z == 0) ? g_Qh : (z == 1) ? g_Kh : g_Vh;
    const __half* W = (z == 0) ? g_WQ : (z == 1) ? g_WK : g_WV;
    __half* C       = (z == 0) ? qh   : (z == 1) ? kh   : vh;
    proj_body(A, W, C, 1, (z == 0) ? SMSC : 1.0f);
}

__global__ void __launch_bounds__(256, 2)
out_proj_kernel(float* __restrict__ C)
{
    proj_body(g_attn, g_WO, C, 0, 1.0f);
}

// ---------------------------------------------------------------------------
// Flash attention (split-KV): fp16 MMA, bias-free softmax, P in registers,
// l via ones-MMA. Block = (b,h) x 128 q-rows x HALF the kv range
// (blockIdx.z selects half). Writes unnormalized fp32 partial O + partial l.
// Grid 1024 CTAs at 3/SM -> better wave packing than 512 (tail halved).
// ---------------------------------------------------------------------------
#define FSTH 72

__global__ void __launch_bounds__(128, 3)
flash_tc_kernel(const uint32_t* __restrict__ mbits)
{
    extern __shared__ __half fsm[];
    __half* qs  = fsm;                    // [128][72]: Q staging (prologue only)
    __half* ksb = fsm + 128 * FSTH;       // [2][64][72]
    __half* vsb = ksb + 2 * 64 * FSTH;    // [2][64][72]

    const int tid  = threadIdx.x;
    const int lane = tid & 31;
    const int w    = tid >> 5;            // 0..3
    const int gid  = lane >> 2;
    const int tig  = lane & 3;
    const int bh   = blockIdx.y;
    const int b    = bh >> 4;
    const int q0   = blockIdx.x * 128;
    const int z    = blockIdx.z;          // kv half

    const __half* qp = g_qh + (size_t)bh * SS * DD;
    const __half* kp = g_kh + (size_t)bh * SS * DD;
    const __half* vp = g_vh + (size_t)bh * SS * DD;

    const uint32_t* mrow[2][2];
    #pragma unroll
    for (int u = 0; u < 2; u++)
        #pragma unroll
        for (int v = 0; v < 2; v++)
            mrow[u][v] = mbits +
                ((size_t)(b * SS + q0 + w * 32 + u * 16 + gid + v * 8) << 6);

    auto load_kv = [&](int st, int kv0) {
        __half* ks = ksb + st * 64 * FSTH;
        __half* vs = vsb + st * 64 * FSTH;
        #pragma unroll
        for (int p = 0; p < 4; p++) {
            int idx = tid + p * 128;
            int r = idx >> 3, c = (idx & 7) * 8;
            cpa16(&ks[r * FSTH + c], &kp[(size_t)(kv0 + r) * DD + c]);
            cpa16(&vs[r * FSTH + c], &vp[(size_t)(kv0 + r) * DD + c]);
        }
    };

    // stage Q
    #pragma unroll
    for (int p = 0; p < 8; p++) {
        int idx = tid + p * 128;
        int r = idx >> 3, c = (idx & 7) * 8;
        cpa16(&qs[r * FSTH + c], &qp[(size_t)(q0 + r) * DD + c]);
    }
    const int T0 = z * 16;      // first 64-row kv tile of this half
    load_kv(0, T0 * 64);
    cp_commit();
    cp_wait<0>();
    __syncthreads();

    // persistent Q fragments (own 32 rows)
    uint32_t qa[2][4][4];
    #pragma unroll
    for (int u = 0; u < 2; u++) {
        int row = w * 32 + u * 16 + (lane & 15);
        #pragma unroll
        for (int t = 0; t < 4; t++)
            ldsm4(qa[u][t], smaddr(&qs[row * FSTH + t * 16 + (lane >> 4) * 8]));
    }

    float o[2][8][4] = {};
    float lacc[2][4] = {};

    const int T1 = T0 + 16;     // 16 tiles per half
    for (int t = T0; t < T1; t++) {
        cp_wait<0>();
        __syncthreads();
        if (t + 1 < T1) load_kv((t + 1) & 1, (t + 1) * 64);
        cp_commit();

        const __half* ks = ksb + (t & 1) * 64 * FSTH;
        const __half* vs = vsb + (t & 1) * 64 * FSTH;

        #pragma unroll
        for (int hh = 0; hh < 2; hh++) {
            float s[2][4][4] = {};
            #pragma unroll
            for (int tt = 0; tt < 4; tt++) {
                #pragma unroll
                for (int jl = 0; jl < 2; jl++) {
                    int jp = 2 * hh + jl;
                    uint32_t kf[4];
                    int nrow = jp * 16 + ((lane >> 4) & 1) * 8 + (lane & 7);
                    int kcol = tt * 16 + ((lane >> 3) & 1) * 8;
                    ldsm4(kf, smaddr(&ks[nrow * FSTH + kcol]));
                    #pragma unroll
                    for (int u = 0; u < 2; u++) {
                        mmaf16(s[u][2 * jl],     qa[u][tt], kf[0], kf[1]);
                        mmaf16(s[u][2 * jl + 1], qa[u][tt], kf[2], kf[3]);
                    }
                }
            }

            const int wq = t * 2 + hh;
            #pragma unroll
            for (int ttl = 0; ttl < 2; ttl++) {
                const int j0 = 2 * ttl, j1 = 2 * ttl + 1;
                const int c00 = j0 * 8 + tig * 2;
                const int c01 = j1 * 8 + tig * 2;
                const int gtt = hh * 2 + ttl;
                uint32_t pa[2][4];
                #pragma unroll
                for (int u = 0; u < 2; u++) {
                    uint32_t wa = mrow[u][0][wq];
                    uint32_t wb = mrow[u][1][wq];
                    pa[u][0] = packh2(ex2(s[u][j0][0]), ex2(s[u][j0][1])) & zm2((wa >> c00) & 3u);
                    pa[u][1] = packh2(ex2(s[u][j0][2]), ex2(s[u][j0][3])) & zm2((wb >> c00) & 3u);
                    pa[u][2] = packh2(ex2(s[u][j1][0]), ex2(s[u][j1][1])) & zm2((wa >> c01) & 3u);
                    pa[u][3] = packh2(ex2(s[u][j1][2]), ex2(s[u][j1][3])) & zm2((wb >> c01) & 3u);
                    mmaf16(lacc[u], pa[u], ONES2, ONES2);
                }
                #pragma unroll
                for (int jp = 0; jp < 4; jp++) {
                    uint32_t vf[4];
                    int kvrow = gtt * 16 + ((lane >> 3) & 1) * 8 + (lane & 7);
                    int dcol  = jp * 16 + ((lane >> 4) & 1) * 8;
                    ldsm4t(vf, smaddr(&vs[kvrow * FSTH + dcol]));
                    #pragma unroll
                    for (int u = 0; u < 2; u++) {
                        mmaf16(o[u][2 * jp],     pa[u], vf[0], vf[1]);
                        mmaf16(o[u][2 * jp + 1], pa[u], vf[2], vf[3]);
                    }
                }
            }
        }
    }

    // write unnormalized fp32 partials (disjoint per z; no atomics)
    #pragma unroll
    for (int u = 0; u < 2; u++) {
        int row = q0 + w * 32 + u * 16 + gid;
        size_t base0 = ((size_t)bh * SS + row) * DD;
        size_t base1 = ((size_t)bh * SS + row + 8) * DD;
        #pragma unroll
        for (int j = 0; j < 8; j++) {
            int d = j * 8 + tig * 2;
            *(float2*)&g_po[z][base0 + d] = make_float2(o[u][j][0], o[u][j][1]);
            *(float2*)&g_po[z][base1 + d] = make_float2(o[u][j][2], o[u][j][3]);
        }
        if (tig == 0) {
            g_pl[z][(size_t)bh * SS + row]     = lacc[u][0];
            g_pl[z][(size_t)bh * SS + row + 8] = lacc[u][2];
        }
    }
}

// ---------------------------------------------------------------------------
// combine: g_attn[b,s,h*64+d] = fp16((O0+O1) / (l0+l1))
// block = 128 threads = 8 s-rows x 16 float4 d-chunks; grid (SS/8, BB*HH)
// ---------------------------------------------------------------------------
__global__ void __launch_bounds__(128)
combine_kernel()
{
    const int bh = blockIdx.y;
    const int b = bh >> 4, h = bh & 15;
    const int tid = threadIdx.x;
    const int r  = tid >> 4;            // 0..7
    const int dc = (tid & 15) * 4;      // 0..60
    const int s  = blockIdx.x * 8 + r;

    size_t pbase = ((size_t)bh * SS + s) * DD + dc;
    float l = g_pl[0][(size_t)bh * SS + s] + g_pl[1][(size_t)bh * SS + s];
    float inv = __frcp_rn(l);
    float4 a = *(float4*)&g_po[0][pbase];
    float4 c = *(float4*)&g_po[1][pbase];
    __half2 h0 = __floats2half2_rn((a.x + c.x) * inv, (a.y + c.y) * inv);
    __half2 h1 = __floats2half2_rn((a.z + c.z) * inv, (a.w + c.w) * inv);
    *(uint2*)&g_attn[((size_t)(b * SS + s)) * EE + h * 64 + dc] =
        make_uint2(*(uint32_t*)&h0, *(uint32_t*)&h1);
}

// ---------------------------------------------------------------------------
extern "C" void kernel_launch(void* const* d_in, const int* in_sizes, int n_in,
                              void* d_out, int out_size)
{
    (void)in_sizes; (void)n_in; (void)out_size;
    const float* Q    = (const float*)d_in[0];
    const float* K    = (const float*)d_in[1];
    const float* V    = (const float*)d_in[2];
    const int*   mask = (const int*)  d_in[3];
    const float* WQ   = (const float*)d_in[4];
    const float* WK   = (const float*)d_in[5];
    const float* WV   = (const float*)d_in[6];
    const float* WO   = (const float*)d_in[7];
    float* out = (float*)d_out;

    __half *qh, *kh, *vh;
    uint32_t* mbits;
    cudaGetSymbolAddress((void**)&qh,    g_qh);
    cudaGetSymbolAddress((void**)&kh,    g_kh);
    cudaGetSymbolAddress((void**)&vh,    g_vh);
    cudaGetSymbolAddress((void**)&mbits, g_mbits);

    const int PROJ_SMEM  = STAGES * (128 + 128) * PSTH * (int)sizeof(__half);   // 61440
    const int FLASH_SMEM = (128 + 4 * 64) * FSTH * (int)sizeof(__half);         // 55296
    cudaFuncSetAttribute(qkv_proj_kernel,
                         cudaFuncAttributeMaxDynamicSharedMemorySize, PROJ_SMEM);
    cudaFuncSetAttribute(out_proj_kernel,
                         cudaFuncAttributeMaxDynamicSharedMemorySize, PROJ_SMEM);
    cudaFuncSetAttribute(flash_tc_kernel,
                         cudaFuncAttributeMaxDynamicSharedMemorySize, FLASH_SMEM);

    pack_mask_kernel<<<BB * SS * SS / 256, 256>>>(mask, mbits);
    cvt_kernel<<<dim3(1024, 16), 256>>>(Q, K, V, WQ, WK, WV, WO);

    qkv_proj_kernel<<<dim3(EE / 128, MTOT / 128, 3), 256, PROJ_SMEM>>>(qh, kh, vh);

    flash_tc_kernel<<<dim3(SS / 128, BB * HH, 2), 128, FLASH_SMEM>>>(mbits);

    combine_kernel<<<dim3(SS / 8, BB * HH), 128>>>();

    out_proj_kernel<<<dim3(EE / 128, MTOT / 128), 256, PROJ_SMEM>>>(out);
}